// round 4
// baseline (speedup 1.0000x reference)
#include <cuda_runtime.h>
#include <math.h>

// ---------------------------------------------------------------------------
// Rotation-equivariant LeNet forward, fp32 direct convs, fused BN(train)+ReLU.
// All rotation convs reduce to plain 3x3 convs with permuted-tap / rolled-
// channel weights (precomputed on device). All BNs are per-channel over
// (B,H,W) with gamma/beta indexed by c % (C/r).
// ---------------------------------------------------------------------------

#define NB_IMG 2048

// Tap destination permutation per rotation i: dest_tap = DST[i][src_tap].
// Derived from np.around(loc @ R(2*pi*i/8)) and ker[m - y, m - x] scatter.
__device__ const int c_DST[8][9] = {
    {8,7,6,5,4,3,2,1,0},
    {5,8,7,2,4,6,1,0,3},
    {2,5,8,1,4,7,0,3,6},
    {1,2,5,0,4,8,3,6,7},
    {0,1,2,3,4,5,6,7,8},
    {3,0,1,6,4,2,7,8,5},
    {6,3,0,7,4,1,8,5,2},
    {7,6,3,8,4,0,5,2,1},
};

// Scratch (static device globals; no allocations allowed).
__device__ float  g_bufA[NB_IMG * 16 * 28 * 28];   // z1 / z4 / z6
__device__ float  g_bufB[NB_IMG * 16 * 28 * 28];   // z2 / z5
__device__ float  g_bufC[NB_IMG * 32 * 14 * 14];   // z3
__device__ float  g_rotK1[16 * 1 * 9];
__device__ float  g_rotK2[16 * 16 * 9];
__device__ float  g_rotK3[32 * 16 * 9];
__device__ float2 g_aff[6][64];                    // per-layer (scale, shift)
__device__ double g_partS[2048];
__device__ double g_partQ[2048];
__device__ double g_nmsPart[1024];

// ---------------------------------------------------------------------------
// Build rotated weight tensors.
// ---------------------------------------------------------------------------
__global__ void build_rot_kernel(const float* __restrict__ w1,
                                 const float* __restrict__ w2,
                                 const float* __restrict__ w3) {
    int tid = threadIdx.x;
    // K1: separate=True, cin=1: rotK1[(i*2+o)][0][DST[i][t]] = w1[o][0][t]
    for (int e = tid; e < 8 * 2 * 9; e += blockDim.x) {
        int i = e / 18, o = (e / 9) % 2, t = e % 9;
        g_rotK1[(i * 2 + o) * 9 + c_DST[i][t]] = w1[o * 9 + t];
    }
    // K2: oc_r=2, cin=16, roll blocks of 2 by i
    for (int e = tid; e < 16 * 16 * 9; e += blockDim.x) {
        int O = e / 144, c = (e % 144) / 9, t = e % 9;
        int i = O / 2, o = O % 2;
        int src_c = (((c >> 1) - i) & 7) * 2 + (c & 1);
        g_rotK2[O * 144 + c * 9 + c_DST[i][t]] = w2[o * 144 + src_c * 9 + t];
    }
    // K3: oc_r=4, cin=16, roll blocks of 2 by i
    for (int e = tid; e < 32 * 16 * 9; e += blockDim.x) {
        int O = e / 144, c = (e % 144) / 9, t = e % 9;
        int i = O / 4, o = O % 4;
        int src_c = (((c >> 1) - i) & 7) * 2 + (c & 1);
        g_rotK3[O * 144 + c * 9 + c_DST[i][t]] = w3[o * 144 + src_c * 9 + t];
    }
}

// ---------------------------------------------------------------------------
// Generic fused conv: input = [B][CIN][HIN][WIN] raw pre-BN values; applies
// affine+ReLU (if AFF) and POOLxPOOL max-pool while staging into smem, then
// 3x3 conv (pad 1) producing raw [B][COUT][HP][WP].
// Block = one image. Thread = (oc-group, position-slot).
// ---------------------------------------------------------------------------
template <int CIN, int CINB, int COUT, int OCG, int HIN, int WIN, int POOL,
          bool AFF, int AFFIDX>
__global__ void __launch_bounds__(256)
conv3x3_kernel(const float* __restrict__ in, const float* __restrict__ wts,
               float* __restrict__ out) {
    constexpr int HP = HIN / POOL, WP = WIN / POOL;
    constexpr int TW = WP + 2, TH = HP + 2, TILE = TW * TH;
    constexpr int NOC = COUT / OCG;
    constexpr int PGRP = 256 / OCG;
    constexpr int NPOS = HP * WP;
    constexpr int NP = (NPOS + PGRP - 1) / PGRP;

    __shared__ float s_tile[CINB * TILE];
    __shared__ float s_w[COUT * CINB * 9];

    const int tid = threadIdx.x;
    const int b = blockIdx.x;
    const float* inb = in + (size_t)b * CIN * HIN * WIN;

    const int ocg = tid / PGRP;
    const int lp = tid % PGRP;

    int pbase[NP];
    bool pval[NP];
#pragma unroll
    for (int k = 0; k < NP; k++) {
        int p = lp + k * PGRP;
        pval[k] = (p < NPOS);
        int pp = pval[k] ? p : 0;
        pbase[k] = (pp / WP) * TW + (pp % WP);
    }

    float acc[NOC][NP];
#pragma unroll
    for (int j = 0; j < NOC; j++)
#pragma unroll
        for (int k = 0; k < NP; k++) acc[j][k] = 0.f;

    for (int cb = 0; cb < CIN; cb += CINB) {
        __syncthreads();
        // stage input tile (affine+relu+pool fused)
        for (int e = tid; e < CINB * TILE; e += 256) {
            int c = e / TILE, r = e % TILE;
            int iy = r / TW - 1, ix = r % TW - 1;
            float v = 0.f;
            if (iy >= 0 && iy < HP && ix >= 0 && ix < WP) {
                int cg = cb + c;
                const float* p = inb + cg * HIN * WIN;
                float a = 1.f, sh = 0.f;
                if constexpr (AFF) {
                    float2 ab = g_aff[AFFIDX][cg];
                    a = ab.x; sh = ab.y;
                }
                if constexpr (POOL == 1) {
                    float x0 = p[iy * WIN + ix];
                    if constexpr (AFF) x0 = fmaxf(fmaf(x0, a, sh), 0.f);
                    v = x0;
                } else {
                    const float* q = p + (2 * iy) * WIN + 2 * ix;
                    float x0 = q[0], x1 = q[1], x2 = q[WIN], x3 = q[WIN + 1];
                    if constexpr (AFF) {
                        x0 = fmaxf(fmaf(x0, a, sh), 0.f);
                        x1 = fmaxf(fmaf(x1, a, sh), 0.f);
                        x2 = fmaxf(fmaf(x2, a, sh), 0.f);
                        x3 = fmaxf(fmaf(x3, a, sh), 0.f);
                    }
                    v = fmaxf(fmaxf(x0, x1), fmaxf(x2, x3));
                }
            }
            s_tile[e] = v;
        }
        // stage weights for this cin chunk
        for (int e = tid; e < COUT * CINB * 9; e += 256) {
            int oc = e / (CINB * 9), rr = e % (CINB * 9);
            int c = rr / 9, t = rr % 9;
            s_w[e] = wts[(oc * CIN + cb + c) * 9 + t];
        }
        __syncthreads();

        const float* wrow = s_w + (size_t)(ocg * NOC) * CINB * 9;
        for (int c = 0; c < CINB; c++) {
            const float* tc = s_tile + c * TILE;
            const float* wc = wrow + c * 9;
#pragma unroll
            for (int ky = 0; ky < 3; ky++) {
#pragma unroll
                for (int kx = 0; kx < 3; kx++) {
                    const int toff = ky * TW + kx;
                    float iv[NP];
#pragma unroll
                    for (int k = 0; k < NP; k++) iv[k] = tc[pbase[k] + toff];
#pragma unroll
                    for (int j = 0; j < NOC; j++) {
                        float w = wc[(size_t)j * CINB * 9 + ky * 3 + kx];
#pragma unroll
                        for (int k = 0; k < NP; k++)
                            acc[j][k] = fmaf(iv[k], w, acc[j][k]);
                    }
                }
            }
        }
    }

    float* ob = out + (size_t)b * COUT * NPOS;
#pragma unroll
    for (int j = 0; j < NOC; j++) {
        int oc = ocg * NOC + j;
#pragma unroll
        for (int k = 0; k < NP; k++)
            if (pval[k]) ob[(size_t)oc * NPOS + lp + k * PGRP] = acc[j][k];
    }
}

// ---------------------------------------------------------------------------
// BN statistics: deterministic two-stage (block partials -> finalize).
// ---------------------------------------------------------------------------
template <int C, int HW, int NBLK>
__global__ void stats_stage1(const float* __restrict__ z) {
    const int c = blockIdx.x / NBLK, j = blockIdx.x % NBLK;
    const int N = NB_IMG * HW;
    double s = 0.0, q = 0.0;
    for (int idx = j * 256 + threadIdx.x; idx < N; idx += NBLK * 256) {
        int bb = idx / HW, pos = idx % HW;
        float v = z[((size_t)bb * C + c) * HW + pos];
        s += v;
        q += (double)v * v;
    }
    __shared__ double ss[256], sq[256];
    ss[threadIdx.x] = s; sq[threadIdx.x] = q;
    __syncthreads();
    for (int st = 128; st > 0; st >>= 1) {
        if (threadIdx.x < st) {
            ss[threadIdx.x] += ss[threadIdx.x + st];
            sq[threadIdx.x] += sq[threadIdx.x + st];
        }
        __syncthreads();
    }
    if (threadIdx.x == 0) {
        g_partS[blockIdx.x] = ss[0];
        g_partQ[blockIdx.x] = sq[0];
    }
}

template <int C, int HW, int NBLK, int GC, int AFFIDX>
__global__ void stats_stage2(const float* __restrict__ gam,
                             const float* __restrict__ bet) {
    const int c = blockIdx.x;
    __shared__ double ss[128], sq[128];
    int t = threadIdx.x;
    ss[t] = (t < NBLK) ? g_partS[c * NBLK + t] : 0.0;
    sq[t] = (t < NBLK) ? g_partQ[c * NBLK + t] : 0.0;
    __syncthreads();
    for (int st = 64; st > 0; st >>= 1) {
        if (t < st) { ss[t] += ss[t + st]; sq[t] += sq[t + st]; }
        __syncthreads();
    }
    if (t == 0) {
        double N = (double)NB_IMG * HW;
        double mean = ss[0] / N;
        double var = sq[0] / N - mean * mean;
        double scale = (double)gam[c % GC] / sqrt(var + 1e-5);
        double shift = (double)bet[c % GC] - mean * scale;
        g_aff[AFFIDX][c] = make_float2((float)scale, (float)shift);
    }
}

// ---------------------------------------------------------------------------
// NMS scalar: mean over [B,4,8,14,14] of v * (v != rot-group max),
// where v = relu(bn3(z3)). Groups are 8 *consecutive* channels (as reference).
// ---------------------------------------------------------------------------
__global__ void nms_stage1(const float* __restrict__ z3) {
    const int TOT = NB_IMG * 4 * 196;
    double s = 0.0;
    for (int idx = blockIdx.x * 256 + threadIdx.x; idx < TOT;
         idx += gridDim.x * 256) {
        int bb = idx / (4 * 196), rr = idx % (4 * 196);
        int g = rr / 196, pos = rr % 196;
        const float* base = z3 + ((size_t)bb * 32 + g * 8) * 196 + pos;
        float v[8];
        float m = -1e30f;
#pragma unroll
        for (int r = 0; r < 8; r++) {
            float2 ab = g_aff[2][g * 8 + r];
            v[r] = fmaxf(fmaf(base[(size_t)r * 196], ab.x, ab.y), 0.f);
            m = fmaxf(m, v[r]);
        }
        float loc = 0.f;
#pragma unroll
        for (int r = 0; r < 8; r++)
            if (v[r] != m) loc += v[r];
        s += loc;
    }
    __shared__ double sd[256];
    sd[threadIdx.x] = s;
    __syncthreads();
    for (int st = 128; st > 0; st >>= 1) {
        if (threadIdx.x < st) sd[threadIdx.x] += sd[threadIdx.x + st];
        __syncthreads();
    }
    if (threadIdx.x == 0) g_nmsPart[blockIdx.x] = sd[0];
}

__global__ void nms_stage2(float* __restrict__ dst) {
    __shared__ double sd[256];
    int t = threadIdx.x;
    double s = 0.0;
    for (int i = t; i < 1024; i += 256) s += g_nmsPart[i];
    sd[t] = s;
    __syncthreads();
    for (int st = 128; st > 0; st >>= 1) {
        if (t < st) sd[t] += sd[t + st];
        __syncthreads();
    }
    if (t == 0) dst[0] = (float)(sd[0] / 12845056.0);  // 2048*32*196
}

// ---------------------------------------------------------------------------
// Head: relu(bn6(z6)) -> maxpool2 pad1 (7->4) -> conv 4x4 pad2 (->5x5)
// -> +bias -> global max -> logits [B,10]
// ---------------------------------------------------------------------------
__global__ void __launch_bounds__(256)
head_kernel(const float* __restrict__ z6, const float* __restrict__ w7,
            const float* __restrict__ b7, float* __restrict__ outp) {
    __shared__ float sp[64 * 16];        // pooled [64][4][4]
    __shared__ float sw[10 * 64 * 16];   // w7
    __shared__ float so[256];            // conv outputs [10][5][5]

    const int b = blockIdx.x, tid = threadIdx.x;
    const float* zb = z6 + (size_t)b * 64 * 49;

    for (int e = tid; e < 1024; e += 256) {
        int c = e / 16, cell = e % 16;
        int py = cell / 4, px = cell % 4;
        float2 ab = g_aff[5][c];
        float m = -1e30f;
#pragma unroll
        for (int dy = 0; dy < 2; dy++) {
#pragma unroll
            for (int dx = 0; dx < 2; dx++) {
                int iy = 2 * py - 1 + dy, ix = 2 * px - 1 + dx;
                if (iy >= 0 && iy < 7 && ix >= 0 && ix < 7) {
                    float v = fmaxf(fmaf(zb[c * 49 + iy * 7 + ix], ab.x, ab.y), 0.f);
                    m = fmaxf(m, v);
                }
            }
        }
        sp[e] = m;
    }
    for (int e = tid; e < 10240; e += 256) sw[e] = w7[e];
    __syncthreads();

    float accv = 0.f;
    if (tid < 250) {
        const int o = tid / 25, ij = tid % 25;
        const int oi = ij / 5, oj = ij % 5;
        for (int c = 0; c < 64; c++) {
            const float* wc = sw + (o * 64 + c) * 16;
            const float* pc = sp + c * 16;
#pragma unroll
            for (int ki = 0; ki < 4; ki++) {
                int yy = oi + ki - 2;
                if (yy < 0 || yy > 3) continue;
#pragma unroll
                for (int kj = 0; kj < 4; kj++) {
                    int xx = oj + kj - 2;
                    if (xx < 0 || xx > 3) continue;
                    accv = fmaf(pc[yy * 4 + xx], wc[ki * 4 + kj], accv);
                }
            }
        }
    }
    so[tid] = accv;
    __syncthreads();
    if (tid < 10) {
        float m = -1e30f;
        for (int q = 0; q < 25; q++) m = fmaxf(m, so[tid * 25 + q]);
        outp[(size_t)b * 10 + tid] = m + b7[tid];
    }
}

// ---------------------------------------------------------------------------
// Launch sequence.
// ---------------------------------------------------------------------------
extern "C" void kernel_launch(void* const* d_in, const int* in_sizes, int n_in,
                              void* d_out, int out_size) {
    (void)in_sizes; (void)n_in; (void)out_size;
    const float* x  = (const float*)d_in[0];
    const float* w1 = (const float*)d_in[1];
    const float* w2 = (const float*)d_in[2];
    const float* w3 = (const float*)d_in[3];
    const float* w4 = (const float*)d_in[4];
    const float* w5 = (const float*)d_in[5];
    const float* w6 = (const float*)d_in[6];
    const float* w7 = (const float*)d_in[7];
    const float* g1 = (const float*)d_in[8];
    const float* b1 = (const float*)d_in[9];
    const float* g2 = (const float*)d_in[10];
    const float* b2 = (const float*)d_in[11];
    const float* g3 = (const float*)d_in[12];
    const float* b3 = (const float*)d_in[13];
    const float* g4 = (const float*)d_in[14];
    const float* b4 = (const float*)d_in[15];
    const float* g5 = (const float*)d_in[16];
    const float* b5 = (const float*)d_in[17];
    const float* g6 = (const float*)d_in[18];
    const float* b6 = (const float*)d_in[19];
    const float* b7 = (const float*)d_in[20];
    float* out = (float*)d_out;

    float *bufA = nullptr, *bufB = nullptr, *bufC = nullptr;
    float *rk1 = nullptr, *rk2 = nullptr, *rk3 = nullptr;
    cudaGetSymbolAddress((void**)&bufA, g_bufA);
    cudaGetSymbolAddress((void**)&bufB, g_bufB);
    cudaGetSymbolAddress((void**)&bufC, g_bufC);
    cudaGetSymbolAddress((void**)&rk1, g_rotK1);
    cudaGetSymbolAddress((void**)&rk2, g_rotK2);
    cudaGetSymbolAddress((void**)&rk3, g_rotK3);

    build_rot_kernel<<<1, 256>>>(w1, w2, w3);

    // L1: conv1 (1->16, 28x28), stats, affine to g_aff[0]
    conv3x3_kernel<1, 1, 16, 1, 28, 28, 1, false, 0><<<NB_IMG, 256>>>(x, rk1, bufA);
    stats_stage1<16, 784, 128><<<16 * 128, 256>>>(bufA);
    stats_stage2<16, 784, 128, 2, 0><<<16, 128>>>(g1, b1);

    // L2: conv2 (16->16, 28x28)
    conv3x3_kernel<16, 8, 16, 1, 28, 28, 1, true, 0><<<NB_IMG, 256>>>(bufA, rk2, bufB);
    stats_stage1<16, 784, 128><<<16 * 128, 256>>>(bufB);
    stats_stage2<16, 784, 128, 2, 1><<<16, 128>>>(g2, b2);

    // L3: pool2 + conv3 (16->32, 14x14)
    conv3x3_kernel<16, 16, 32, 2, 28, 28, 2, true, 1><<<NB_IMG, 256>>>(bufB, rk3, bufC);
    stats_stage1<32, 196, 64><<<32 * 64, 256>>>(bufC);
    stats_stage2<32, 196, 64, 4, 2><<<32, 128>>>(g3, b3);

    // NMS scalar from relu(bn3(z3))
    nms_stage1<<<1024, 256>>>(bufC);
    nms_stage2<<<1, 256>>>(out + NB_IMG * 10);

    // L4: conv4 (32->32, 14x14)
    conv3x3_kernel<32, 16, 32, 2, 14, 14, 1, true, 2><<<NB_IMG, 256>>>(bufC, w4, bufA);
    stats_stage1<32, 196, 64><<<32 * 64, 256>>>(bufA);
    stats_stage2<32, 196, 64, 32, 3><<<32, 128>>>(g4, b4);

    // L5: pool2 + conv5 (32->64, 7x7)
    conv3x3_kernel<32, 16, 64, 4, 14, 14, 2, true, 3><<<NB_IMG, 256>>>(bufA, w5, bufB);
    stats_stage1<64, 49, 32><<<64 * 32, 256>>>(bufB);
    stats_stage2<64, 49, 32, 64, 4><<<64, 128>>>(g5, b5);

    // L6: conv6 (64->64, 7x7)
    conv3x3_kernel<64, 16, 64, 4, 7, 7, 1, true, 4><<<NB_IMG, 256>>>(bufB, w6, bufA);
    stats_stage1<64, 49, 32><<<64 * 32, 256>>>(bufA);
    stats_stage2<64, 49, 32, 64, 5><<<64, 128>>>(g6, b6);

    // Head: pool(pad1) + conv7 + bias + global max
    head_kernel<<<NB_IMG, 256>>>(bufA, w7, b7, out);
}